// round 4
// baseline (speedup 1.0000x reference)
#include <cuda_runtime.h>
#include <cstdint>

#define GG   128
#define AA   100
#define WIN  10
#define FDIM 16
#define HD   128
#define K1   (WIN*FDIM)   // 160
#define NN   (GG*AA)      // 12800

typedef unsigned long long ull;

// ---- packed f32x2 helpers ----
__device__ __forceinline__ ull pk2(float lo, float hi) {
    ull r; asm("mov.b64 %0, {%1,%2};" : "=l"(r) : "f"(lo), "f"(hi)); return r;
}
__device__ __forceinline__ ull fma2(ull a, ull b, ull c) {
    ull d; asm("fma.rn.f32x2 %0, %1, %2, %3;" : "=l"(d) : "l"(a), "l"(b), "l"(c)); return d;
}
__device__ __forceinline__ ull add2(ull a, ull b) {
    ull d; asm("add.rn.f32x2 %0, %1, %2;" : "=l"(d) : "l"(a), "l"(b)); return d;
}
__device__ __forceinline__ float2 upk2(ull v) {
    float lo, hi; asm("mov.b64 {%0,%1}, %2;" : "=f"(lo), "=f"(hi) : "l"(v));
    return make_float2(lo, hi);
}

// ---- gmem scratch (device globals) ----
__device__ __align__(16) ull   g_xdup[(size_t)NN*K1];   // x duplicated pairs, 16.4 MB
__device__ __align__(16) float g_h   [(size_t)NN*HD];   // h3 for conv kernel

// ---------------------------------------------------------------------------
// Pre-kernel: duplicate x into pair format
// ---------------------------------------------------------------------------
__global__ void __launch_bounds__(256) xdup_kernel(const float* __restrict__ x)
{
    const size_t i = (size_t)blockIdx.x*256 + threadIdx.x;   // grid sized exactly
    const float v = x[i];
    g_xdup[i] = pk2(v, v);
}

// ---------------------------------------------------------------------------
// Scheme A warp tile (cols packed): C[r][c-pairs] = sum_k Adup[r][k] * B[k][c]
// Adup: element k of row r is a duplicated (a,a) ull (broadcast load, 1 wf).
// B: natural ulonglong2 pairs. Zero MOVs in the mainloop.
// ---------------------------------------------------------------------------
template<int K, int R>
__device__ __forceinline__ void schemeA_tile(const ull* __restrict__ Ad, int rowStart,
                                             const ulonglong2* __restrict__ B2,
                                             float* __restrict__ Pout, int lane)
{
    ull acc[R][2];
#pragma unroll
    for (int r = 0; r < R; r++) { acc[r][0] = 0ull; acc[r][1] = 0ull; }

#pragma unroll 1
    for (int j4 = 0; j4 < K/4; j4++) {
        const ulonglong2 b0 = B2[(4*j4+0)*32 + lane];
        const ulonglong2 b1 = B2[(4*j4+1)*32 + lane];
        const ulonglong2 b2 = B2[(4*j4+2)*32 + lane];
        const ulonglong2 b3 = B2[(4*j4+3)*32 + lane];
#pragma unroll
        for (int r = 0; r < R; r++) {
            const ulonglong2* ap =
                reinterpret_cast<const ulonglong2*>(Ad + (size_t)(rowStart+r)*K + 4*j4);
            const ulonglong2 aA = ap[0];   // (a0,a0),(a1,a1)
            const ulonglong2 aB = ap[1];   // (a2,a2),(a3,a3)
            acc[r][0] = fma2(aA.x, b0.x, acc[r][0]); acc[r][1] = fma2(aA.x, b0.y, acc[r][1]);
            acc[r][0] = fma2(aA.y, b1.x, acc[r][0]); acc[r][1] = fma2(aA.y, b1.y, acc[r][1]);
            acc[r][0] = fma2(aB.x, b2.x, acc[r][0]); acc[r][1] = fma2(aB.x, b2.y, acc[r][1]);
            acc[r][0] = fma2(aB.y, b3.x, acc[r][0]); acc[r][1] = fma2(aB.y, b3.y, acc[r][1]);
        }
    }
#pragma unroll
    for (int r = 0; r < R; r++) {
        reinterpret_cast<ulonglong2*>(Pout + (size_t)(rowStart+r)*HD)[lane] =
            make_ulonglong2(acc[r][0], acc[r][1]);
    }
}

template<int K>
__device__ __forceinline__ void schemeA_phase(const ull* __restrict__ Ad,
                                              const float* __restrict__ B,
                                              float* __restrict__ Pout,
                                              int warp, int lane)
{
    const ulonglong2* B2 = reinterpret_cast<const ulonglong2*>(B);
    if (warp < 4) schemeA_tile<K, 7>(Ad, warp*7,          B2, Pout, lane);
    else          schemeA_tile<K, 6>(Ad, 28 + (warp-4)*6, B2, Pout, lane);
}

// ---------------------------------------------------------------------------
// Scheme B warp tile (rows packed): C[(i0,i1)][c] = sum_k adj[i][k]*P[k][c].
// adj symmetric -> A-pair = contiguous broadcast ull from adj row k (no dup).
// B needs per-lane dup packs (4/lane/k). Epilogue: bias+relu, then either
// dup-format smem write (feeds next scheme-A phase) or plain gmem write.
// ---------------------------------------------------------------------------
template<int PR, bool TOGMEM>
__device__ __forceinline__ void schemeB_tile(const float* __restrict__ s_adj,
                                             const float* __restrict__ s_P,
                                             const float* __restrict__ bias,
                                             int pairStart,
                                             ull* __restrict__ s_hd,
                                             float* __restrict__ gout,
                                             int lane)
{
    const int rowStart = 2*pairStart;
    ull acc[PR][4];
#pragma unroll
    for (int p = 0; p < PR; p++)
#pragma unroll
        for (int c = 0; c < 4; c++) acc[p][c] = 0ull;

#pragma unroll 2
    for (int k = 0; k < AA; k++) {
        const ull* ap = reinterpret_cast<const ull*>(s_adj + (size_t)k*AA + rowStart);
        ull a[PR];
#pragma unroll
        for (int p = 0; p < PR; p++) a[p] = ap[p];

        const float4 pv = reinterpret_cast<const float4*>(s_P + (size_t)k*HD)[lane];
        const ull bd0 = pk2(pv.x, pv.x);
        const ull bd1 = pk2(pv.y, pv.y);
        const ull bd2 = pk2(pv.z, pv.z);
        const ull bd3 = pk2(pv.w, pv.w);
#pragma unroll
        for (int p = 0; p < PR; p++) {
            acc[p][0] = fma2(a[p], bd0, acc[p][0]);
            acc[p][1] = fma2(a[p], bd1, acc[p][1]);
            acc[p][2] = fma2(a[p], bd2, acc[p][2]);
            acc[p][3] = fma2(a[p], bd3, acc[p][3]);
        }
    }

    const float4 bb = reinterpret_cast<const float4*>(bias)[lane];
#pragma unroll
    for (int p = 0; p < PR; p++) {
        const int i0 = rowStart + 2*p, i1 = i0 + 1;
        const float2 v0 = upk2(acc[p][0]);
        const float2 v1 = upk2(acc[p][1]);
        const float2 v2 = upk2(acc[p][2]);
        const float2 v3 = upk2(acc[p][3]);
        float4 r0, r1;
        r0.x = fmaxf(v0.x + bb.x, 0.f); r0.y = fmaxf(v1.x + bb.y, 0.f);
        r0.z = fmaxf(v2.x + bb.z, 0.f); r0.w = fmaxf(v3.x + bb.w, 0.f);
        r1.x = fmaxf(v0.y + bb.x, 0.f); r1.y = fmaxf(v1.y + bb.y, 0.f);
        r1.z = fmaxf(v2.y + bb.z, 0.f); r1.w = fmaxf(v3.y + bb.w, 0.f);
        if (TOGMEM) {
            reinterpret_cast<float4*>(gout + (size_t)i0*HD)[lane] = r0;
            reinterpret_cast<float4*>(gout + (size_t)i1*HD)[lane] = r1;
        } else {
            ull* d0 = s_hd + (size_t)i0*HD + 4*lane;
            ull* d1 = s_hd + (size_t)i1*HD + 4*lane;
            d0[0] = pk2(r0.x, r0.x); d0[1] = pk2(r0.y, r0.y);
            d0[2] = pk2(r0.z, r0.z); d0[3] = pk2(r0.w, r0.w);
            d1[0] = pk2(r1.x, r1.x); d1[1] = pk2(r1.y, r1.y);
            d1[2] = pk2(r1.z, r1.z); d1[3] = pk2(r1.w, r1.w);
        }
    }
}

template<bool TOGMEM>
__device__ __forceinline__ void schemeB_phase(const float* __restrict__ s_adj,
                                              const float* __restrict__ s_P,
                                              const float* __restrict__ bias,
                                              ull* __restrict__ s_hd,
                                              float* __restrict__ gout,
                                              int warp, int lane)
{
    // 50 row-pairs: warps 0-1 take 4 pairs, warps 2-15 take 3.
    if (warp < 2) schemeB_tile<4, TOGMEM>(s_adj, s_P, bias, warp*4,        s_hd, gout, lane);
    else          schemeB_tile<3, TOGMEM>(s_adj, s_P, bias, 8+(warp-2)*3, s_hd, gout, lane);
}

// ---------------------------------------------------------------------------
// Fused kernel: adjacency -> 6 GEMM phases. One block per group.
// ---------------------------------------------------------------------------
__global__ void __launch_bounds__(512, 1) fused_kernel(
    const float* __restrict__ x,
    const float* __restrict__ W1, const float* __restrict__ b1,
    const float* __restrict__ W2, const float* __restrict__ b2,
    const float* __restrict__ W3, const float* __restrict__ b3)
{
    extern __shared__ char sm[];
    ull*   s_hd  = reinterpret_cast<ull*>(sm);                 // 100*128 ull = 102400 B
    float* s_P   = reinterpret_cast<float*>(sm + (size_t)AA*HD*8);   // 51200 B
    float* s_adj = s_P + AA*HD;                                // 40000 B

    __shared__ float xc[AA][WIN];
    __shared__ float invd[AA];
    __shared__ float dinv[AA];

    const int g    = blockIdx.x;
    const int tid  = threadIdx.x;
    const int warp = tid >> 5;
    const int lane = tid & 31;

    // ---- Phase 0: adjacency ----
    if (tid < AA) {
        float r[WIN]; float s = 0.f;
#pragma unroll
        for (int t = 0; t < WIN; t++) {
            r[t] = x[((size_t)(g*AA + tid)*WIN + t)*FDIM + (FDIM-1)];
            s += r[t];
        }
        const float mean = s * (1.0f/WIN);
        float ss = 0.f;
#pragma unroll
        for (int t = 0; t < WIN; t++) {
            float v = r[t] - mean;
            xc[tid][t] = v;
            ss += v*v;
        }
        invd[tid] = rsqrtf(ss);
    }
    __syncthreads();

    if (tid < AA) {
        float xi[WIN];
#pragma unroll
        for (int t = 0; t < WIN; t++) xi[t] = xc[tid][t];
        const float di = invd[tid];
        float rs = 0.f;
#pragma unroll 2
        for (int j = 0; j < AA; j++) {
            float dot = 0.f;
#pragma unroll
            for (int t = 0; t < WIN; t++) dot = fmaf(xi[t], xc[j][t], dot);
            float c = dot * di * invd[j];
            rs += 1.0f - fabsf(c);
        }
        dinv[tid] = rsqrtf(rs + 1.0f);
    }
    __syncthreads();

    for (int e = tid; e < AA*AA; e += 512) {
        const int i = e / AA, j = e - i*AA;
        float dot = 0.f;
#pragma unroll
        for (int t = 0; t < WIN; t++) dot = fmaf(xc[i][t], xc[j][t], dot);
        float c = dot * invd[i] * invd[j];
        float a = 1.0f - fabsf(c) + (i == j ? 1.0f : 0.0f);
        s_adj[e] = a * dinv[i] * dinv[j];
    }
    __syncthreads();

    // ---- Phase 1: P = x@W1 (A-dup from gmem) ----
    schemeA_phase<K1>(g_xdup + (size_t)g*AA*K1, W1, s_P, warp, lane);
    __syncthreads();
    // ---- Phase 2: h1 = relu(adj@P + b1) -> s_hd (dup) ----
    schemeB_phase<false>(s_adj, s_P, b1, s_hd, nullptr, warp, lane);
    __syncthreads();
    // ---- Phase 3: P = h1@W2 ----
    schemeA_phase<HD>(s_hd, W2, s_P, warp, lane);
    __syncthreads();
    // ---- Phase 4: h2 = relu(adj@P + b2) -> s_hd (dup) ----
    schemeB_phase<false>(s_adj, s_P, b2, s_hd, nullptr, warp, lane);
    __syncthreads();
    // ---- Phase 5: P = h2@W3 ----
    schemeA_phase<HD>(s_hd, W3, s_P, warp, lane);
    __syncthreads();
    // ---- Phase 6: h3 = relu(adj@P + b3) -> gmem (plain) ----
    schemeB_phase<true>(s_adj, s_P, b3, nullptr, g_h + (size_t)g*AA*HD, warp, lane);
}

// ---------------------------------------------------------------------------
// Conv kernel: fused conv1(relu)+conv2, one warp per row, full-chip grid.
// ---------------------------------------------------------------------------
__global__ void __launch_bounds__(256) conv_kernel(
    const float* __restrict__ cw1, const float* __restrict__ cb1,
    const float* __restrict__ cw2, const float* __restrict__ cb2,
    float* __restrict__ out)
{
    __shared__ ulonglong2 wpk[HD][4];

    const int tid = threadIdx.x;
    if (tid < HD) {
        const float wx = cw1[3*tid+0], wy = cw1[3*tid+1], wz = cw1[3*tid+2];
        const float wb = cb1[tid];
        const float u0 = 0.5f*cw2[3*tid+0], u1 = 0.5f*cw2[3*tid+1], u2 = 0.5f*cw2[3*tid+2];
        wpk[tid][0] = make_ulonglong2(pk2(wx, wx), pk2(wy, wy));
        wpk[tid][1] = make_ulonglong2(pk2(wz, wz), pk2(wb, wb));
        wpk[tid][2] = make_ulonglong2(pk2(u0, u0), pk2(u1, u1));
        wpk[tid][3] = make_ulonglong2(pk2(u2, u2), 0ull);
    }
    __syncthreads();

    const int warp = tid >> 5, lane = tid & 31;
    const int row  = blockIdx.x*8 + warp;

    const float4 hv = reinterpret_cast<const float4*>(g_h + (size_t)row*HD)[lane];
    float hm1 = __shfl_up_sync(0xffffffffu, hv.w, 1);  if (lane == 0)  hm1 = 0.f;
    float hp1 = __shfl_down_sync(0xffffffffu, hv.x, 1); if (lane == 31) hp1 = 0.f;

    const ull Pm = pk2(hm1,  hv.x);
    const ull P0 = pk2(hv.x, hv.y);
    const ull P1 = pk2(hv.y, hv.z);
    const ull P2 = pk2(hv.z, hv.w);
    const ull P3 = pk2(hv.w, hp1);

    const ull M = 0x7FFFFFFF7FFFFFFFull;

    ull T0a = 0ull, T0b = 0ull, T1a = 0ull, T1b = 0ull, T2a = 0ull, T2b = 0ull;

#pragma unroll 4
    for (int c = 0; c < HD; c++) {
        const ulonglong2 q0 = wpk[c][0];
        const ulonglong2 q1 = wpk[c][1];
        const ulonglong2 q2 = wpk[c][2];
        const ull        q3 = wpk[c][3].x;

        ull z01 = fma2(q0.x, Pm, fma2(q0.y, P0, fma2(q1.x, P1, q1.y)));
        ull z23 = fma2(q0.x, P1, fma2(q0.y, P2, fma2(q1.x, P3, q1.y)));

        z01 = add2(z01, z01 & M);   // 2*relu(z); 0.5 folded into u-weights
        z23 = add2(z23, z23 & M);

        T0a = fma2(q2.x, z01, T0a);  T0b = fma2(q2.x, z23, T0b);
        T1a = fma2(q2.y, z01, T1a);  T1b = fma2(q2.y, z23, T1b);
        T2a = fma2(q3,   z01, T2a);  T2b = fma2(q3,   z23, T2b);
    }

    const float2 t0a = upk2(T0a), t0b = upk2(T0b);
    const float2 t1a = upk2(T1a), t1b = upk2(T1b);
    const float2 t2a = upk2(T2a), t2b = upk2(T2b);

    float t0m = __shfl_up_sync(0xffffffffu, t0b.y, 1);  if (lane == 0)  t0m = 0.f;
    float t2p = __shfl_down_sync(0xffffffffu, t2a.x, 1); if (lane == 31) t2p = 0.f;

    const float c2 = cb2[0];
    float4 res;
    res.x = t0m   + t1a.x + t2a.y + c2;
    res.y = t0a.x + t1a.y + t2b.x + c2;
    res.z = t0a.y + t1b.x + t2b.y + c2;
    res.w = t0b.x + t1b.y + t2p   + c2;
    reinterpret_cast<float4*>(out + (size_t)row*HD)[lane] = res;
}

// ---------------------------------------------------------------------------
extern "C" void kernel_launch(void* const* d_in, const int* in_sizes, int n_in,
                              void* d_out, int out_size)
{
    const float* x   = (const float*)d_in[0];
    const float* W1  = (const float*)d_in[1];
    const float* b1  = (const float*)d_in[2];
    const float* W2  = (const float*)d_in[3];
    const float* b2  = (const float*)d_in[4];
    const float* W3  = (const float*)d_in[5];
    const float* b3  = (const float*)d_in[6];
    const float* cw1 = (const float*)d_in[7];
    const float* cb1 = (const float*)d_in[8];
    const float* cw2 = (const float*)d_in[9];
    const float* cb2 = (const float*)d_in[10];
    float* out = (float*)d_out;

    // x-dup pregen: NN*K1 = 2,048,000 elements = 8000 blocks * 256
    xdup_kernel<<<(NN*K1)/256, 256>>>(x);

    const int SMEM = AA*HD*8 + AA*HD*4 + AA*AA*4;   // 193,600 B
    static bool attrSet = false;
    if (!attrSet) {
        cudaFuncSetAttribute(fused_kernel, cudaFuncAttributeMaxDynamicSharedMemorySize, SMEM);
        attrSet = true;
    }
    fused_kernel<<<GG, 512, SMEM>>>(x, W1, b1, W2, b2, W3, b3);

    conv_kernel<<<NN/8, 256>>>(cw1, cb1, cw2, cb2, out);
}